// round 5
// baseline (speedup 1.0000x reference)
#include <cuda_runtime.h>

// dim=4096, MAX_DIM=32, N_COMP=10000.
// gather_idx/gather_sign: [32,32,32] row-major (k,i,j), int32/float32.
// Output: ricci[4096*4096] row-major + scalar trace at index 4096*4096.

#define DIMN 4096
#define MD   32
#define NV4  (DIMN * DIMN / 4)       // 4,194,304 float4 chunks
#define GRID 512
#define TPB  256
#define ITERS (NV4 / (GRID * TPB))   // 32

__global__ __launch_bounds__(TPB)
void ricci_fused_kernel(const float* __restrict__ comp,
                        const int*   __restrict__ gidx,
                        const float* __restrict__ gsgn,
                        float* __restrict__ out)
{
    const int tid = blockIdx.x * TPB + threadIdx.x;   // 0..131071
    float4* __restrict__ out4 = reinterpret_cast<float4*>(out);

    #pragma unroll
    for (int it = 0; it < ITERS; it++) {
        const int idx = tid + it * (GRID * TPB);      // float4 index
        float4 v = make_float4(0.f, 0.f, 0.f, 0.f);

        // Patch region: first 32 rows, cols 0..31 -> idx < 32*1024 and
        // (idx % 1024) < 8. Stride (131072) > 32768, so only it==0 can
        // take this branch; iterations 1..31 are pure zero-fill.
        if (idx < (MD * DIMN / 4) && (idx & (DIMN / 4 - 1)) < (MD / 4)) {
            const int i = idx >> 10;          // row
            const int j = (idx & 1023) << 2;  // col base
            float r0 = 0.f, r1 = 0.f, r2 = 0.f, r3 = 0.f;
            #pragma unroll
            for (int k = 0; k < MD; k++) {
                const int o = k * (MD * MD) + i * MD + j;
                r0 += gsgn[o + 0] * comp[gidx[o + 0]];
                r1 += gsgn[o + 1] * comp[gidx[o + 1]];
                r2 += gsgn[o + 2] * comp[gidx[o + 2]];
                r3 += gsgn[o + 3] * comp[gidx[o + 3]];
            }
            v = make_float4(r0, r1, r2, r3);
        }
        // Streaming store: output is write-once, never re-read by us.
        __stcs(&out4[idx], v);
    }

    // Trace scalar at index DIMN*DIMN: block 0 warp 0, one diagonal
    // element per lane, shuffle-reduce (fixed order -> deterministic).
    if (blockIdx.x == 0 && threadIdx.x < 32) {
        const int t = threadIdx.x;
        float d = 0.f;
        #pragma unroll
        for (int k = 0; k < MD; k++) {
            const int o = k * (MD * MD) + t * MD + t;
            d += gsgn[o] * comp[gidx[o]];
        }
        #pragma unroll
        for (int off = 16; off > 0; off >>= 1)
            d += __shfl_down_sync(0xFFFFFFFFu, d, off);
        if (t == 0) out[(size_t)DIMN * DIMN] = d;
    }
}

extern "C" void kernel_launch(void* const* d_in, const int* in_sizes, int n_in,
                              void* d_out, int out_size)
{
    const float* comp = (const float*)d_in[0];   // components [10000] f32
    const int*   gidx = (const int*)  d_in[1];   // gather_idx [32,32,32] i32
    const float* gsgn = (const float*)d_in[2];   // gather_sign [32,32,32] f32

    float* out = (float*)d_out;

    ricci_fused_kernel<<<GRID, TPB>>>(comp, gidx, gsgn, out);
}

// round 6
// speedup vs baseline: 1.0981x; 1.0981x over previous
#include <cuda_runtime.h>

// dim=4096, MAX_DIM=32, N_COMP=10000.
// gather_idx/gather_sign: [32,32,32] row-major (k,i,j), int32/float32.
// Output: ricci[4096*4096] row-major + scalar trace at index 4096*4096.

#define DIMN 4096
#define MD 32

// One block per row i in [0,32). Threads 0..31 compute the gathered value;
// all 256 threads then write the FULL 4096-float row (values in cols 0..31,
// zeros elsewhere). Block 0 also computes the trace scalar via warp-shuffle
// reduce over redundantly-recomputed diagonal elements (fixed order ->
// deterministic). The concurrent memset covers rows 32..4095 only, so the
// two graph nodes touch disjoint memory.
__global__ __launch_bounds__(256)
void ricci_rows_kernel(const float* __restrict__ comp,
                       const int*   __restrict__ gidx,
                       const float* __restrict__ gsgn,
                       float* __restrict__ out)
{
    __shared__ float sh[MD];

    const int i = blockIdx.x;     // row 0..31
    const int t = threadIdx.x;    // 0..255

    if (t < MD) {
        float r = 0.f;
        #pragma unroll
        for (int k = 0; k < MD; k++) {
            const int o = k * (MD * MD) + i * MD + t;
            r += gsgn[o] * comp[gidx[o]];
        }
        sh[t] = r;
    }
    __syncthreads();

    float4* __restrict__ row4 =
        reinterpret_cast<float4*>(out + (size_t)i * DIMN);
    #pragma unroll
    for (int c = t; c < DIMN / 4; c += 256) {
        float4 v;
        if (c < MD / 4) {
            const int j = c * 4;
            v = make_float4(sh[j], sh[j + 1], sh[j + 2], sh[j + 3]);
        } else {
            v = make_float4(0.f, 0.f, 0.f, 0.f);
        }
        row4[c] = v;
    }

    if (i == 0 && t < 32) {
        float d = 0.f;
        #pragma unroll
        for (int k = 0; k < MD; k++) {
            const int o = k * (MD * MD) + t * MD + t;
            d += gsgn[o] * comp[gidx[o]];
        }
        #pragma unroll
        for (int off = 16; off > 0; off >>= 1)
            d += __shfl_down_sync(0xFFFFFFFFu, d, off);
        if (t == 0) out[(size_t)DIMN * DIMN] = d;
    }
}

extern "C" void kernel_launch(void* const* d_in, const int* in_sizes, int n_in,
                              void* d_out, int out_size)
{
    const float* comp = (const float*)d_in[0];   // components [10000] f32
    const int*   gidx = (const int*)  d_in[1];   // gather_idx [32,32,32] i32
    const float* gsgn = (const float*)d_in[2];   // gather_sign [32,32,32] f32

    float* out = (float*)d_out;

    // One-time host-side resources (no device memory involved). Created on
    // the first (eager correctness) call; reused across capture/replays.
    static cudaStream_t s_side = nullptr;
    static cudaEvent_t  s_fork = nullptr;
    static cudaEvent_t  s_join = nullptr;
    if (s_side == nullptr) {
        cudaStreamCreateWithFlags(&s_side, cudaStreamNonBlocking);
        cudaEventCreateWithFlags(&s_fork, cudaEventDisableTiming);
        cudaEventCreateWithFlags(&s_join, cudaEventDisableTiming);
    }

    // Fork: side stream joins the (possibly capturing) default stream.
    cudaEventRecord(s_fork, 0);
    cudaStreamWaitEvent(s_side, s_fork, 0);

    // Branch A (default stream): zero rows 32..4095. Rows 0..31 and the
    // trailing scalar are fully written by the kernel -> disjoint regions,
    // safe to run concurrently.
    const size_t skip = (size_t)MD * DIMN;                 // 32*4096 floats
    const size_t fill = (size_t)DIMN * DIMN - skip;
    cudaMemsetAsync(out + skip, 0, fill * sizeof(float));

    // Branch B (side stream): gather-reduce patch + trace scalar.
    ricci_rows_kernel<<<MD, 256, 0, s_side>>>(comp, gidx, gsgn, out);

    // Join back to the default stream.
    cudaEventRecord(s_join, s_side);
    cudaStreamWaitEvent(0, s_join, 0);
}